// round 3
// baseline (speedup 1.0000x reference)
#include <cuda_runtime.h>
#include <cuda_bf16.h>
#include <mma.h>

using namespace nvcuda;

// Problem constants
#define NC     64          // channels
#define SS     3136        // 56*56
#define NIMG   128
#define MTOT   (NIMG*SS)   // 401408
#define KT     64          // s-tile width
#define TILES  (NIMG*49)   // 6272 tiles of 64 columns
#define GBLK   448         // gram grid (6272/448 = 14 tiles/block, exact)
#define WBLK   784         // whiten grid (6272/784 = 8 tiles/block, exact)
#define BPITCH 72          // bf16 smem pitch (mult of 8 elems = 16B)
#define FPITCH 68          // fp32 smem pitch (mult of 4 elems = 16B)
#define EPSF   1e-3f

// Scratch (static device globals: allocation-free)
__device__ float          g_partials[GBLK][4160]; // 4096 gram + 64 channel sums
__device__ float          g_G[4160];
__device__ float          g_mean[NC];
__device__ __nv_bfloat16  g_E[NC*NC];             // wm - I, row-major [c_out][c_in]

// ---------------------------------------------------------------------------
// Kernel 1: partial Gram G_b = sum over block's columns of x x^T, + channel sums
// ---------------------------------------------------------------------------
__global__ __launch_bounds__(256) void gram_kernel(const float* __restrict__ X) {
    __shared__ __nv_bfloat16 tb[NC * BPITCH];
    __shared__ float ssum[NC];

    const int t = threadIdx.x, b = blockIdx.x;
    const int warp = t >> 5;
    const int row = t >> 2;          // channel row 0..63 (fixed per thread)
    const int c4  = (t & 3) * 4;     // first float4 index (4 consecutive f4/thread)

    wmma::fragment<wmma::accumulator, 16, 16, 16, float> acc[2];
    wmma::fill_fragment(acc[0], 0.0f);
    wmma::fill_fragment(acc[1], 0.0f);

    float lsum = 0.0f;

    for (int it = 0; it < 14; ++it) {
        const int T  = b + it * GBLK;
        const int n  = T / 49;
        const int s0 = (T % 49) * KT;
        const float4* src = (const float4*)(X + (size_t)n * NC * SS + (size_t)row * SS + s0);
        #pragma unroll
        for (int j = 0; j < 4; ++j) {
            float4 v = src[c4 + j];
            lsum += v.x + v.y + v.z + v.w;
            __nv_bfloat162* dst = (__nv_bfloat162*)&tb[row * BPITCH + (c4 + j) * 4];
            dst[0] = __floats2bfloat162_rn(v.x, v.y);
            dst[1] = __floats2bfloat162_rn(v.z, v.w);
        }
        __syncthreads();
        #pragma unroll
        for (int ot = 0; ot < 2; ++ot) {
            const int Tid = warp * 2 + ot;
            const int r0 = (Tid >> 2) * 16;   // c1 block
            const int q0 = (Tid & 3) * 16;    // c2 block
            #pragma unroll
            for (int k = 0; k < 4; ++k) {
                wmma::fragment<wmma::matrix_a, 16, 16, 16, __nv_bfloat16, wmma::row_major> fa;
                wmma::fragment<wmma::matrix_b, 16, 16, 16, __nv_bfloat16, wmma::col_major> fb;
                wmma::load_matrix_sync(fa, &tb[r0 * BPITCH + k * 16], BPITCH);
                // col-major B with ld=BPITCH: B(k,n) = tb[(q0+n)*BPITCH + k0+k] = X^T block
                wmma::load_matrix_sync(fb, &tb[q0 * BPITCH + k * 16], BPITCH);
                wmma::mma_sync(acc[ot], fa, fb, acc[ot]);
            }
        }
        __syncthreads();
    }

    // channel-sum reduce: 4 consecutive lanes share a row
    lsum += __shfl_down_sync(0xffffffffu, lsum, 2);
    lsum += __shfl_down_sync(0xffffffffu, lsum, 1);
    if ((t & 3) == 0) ssum[row] = lsum;
    __syncthreads();

    #pragma unroll
    for (int ot = 0; ot < 2; ++ot) {
        const int Tid = warp * 2 + ot;
        const int r0 = (Tid >> 2) * 16;
        const int q0 = (Tid & 3) * 16;
        wmma::store_matrix_sync(&g_partials[b][r0 * 64 + q0], acc[ot], 64, wmma::mem_row_major);
    }
    if (t < NC) g_partials[b][4096 + t] = ssum[t];
}

// ---------------------------------------------------------------------------
// Kernel 2: reduce 448 partials -> g_G
// ---------------------------------------------------------------------------
__global__ __launch_bounds__(256) void reduce_kernel() {
    const int i = blockIdx.x * blockDim.x + threadIdx.x;
    if (i < 4160) {
        float s = 0.0f;
        #pragma unroll 4
        for (int b = 0; b < GBLK; ++b) s += g_partials[b][i];
        g_G[i] = s;
    }
}

// ---------------------------------------------------------------------------
// Kernel 3: single-block stats: sigma -> Taylor inverse-sqrt -> E = wm - I (bf16)
// ---------------------------------------------------------------------------
__global__ __launch_bounds__(256) void stats_kernel() {
    __shared__ float sP[4096];   // P = sigma/mu - I
    __shared__ float sQ[4096];   // Q = P*P
    __shared__ float smean[NC];
    __shared__ float sMu, sRs;

    const int t = threadIdx.x;
    const float invm = 1.0f / (float)MTOT;

    if (t < NC) {
        float mn = g_G[4096 + t] * invm;
        smean[t] = mn;
        g_mean[t] = mn;
    }
    __syncthreads();

    // sigma into sP
    for (int i = t; i < 4096; i += 256) {
        int r = i >> 6, c = i & 63;
        sP[i] = g_G[i] * invm - smean[r] * smean[c] + ((r == c) ? EPSF : 0.0f);
    }
    __syncthreads();

    if (t == 0) {
        float tr = 0.0f;
        for (int i = 0; i < NC; ++i) tr += sP[i * 65];
        float mu = tr / (float)NC;
        sMu = mu;
        float rs = rsqrtf(mu);
        rs = rs * (1.5f - 0.5f * mu * rs * rs);  // Newton refine
        sRs = rs;
    }
    __syncthreads();

    const float invmu = 1.0f / sMu;
    for (int i = t; i < 4096; i += 256) {
        int r = i >> 6, c = i & 63;
        sP[i] = sP[i] * invmu - ((r == c) ? 1.0f : 0.0f);
    }
    __syncthreads();

    // Q = P @ P : each thread owns a 4x4 output block (broadcast-friendly reads)
    const int r0 = (t >> 4) * 4;
    const int c0 = (t & 15) * 4;
    {
        float a[4][4] = {};
        for (int k = 0; k < 64; ++k) {
            float pa[4], pb[4];
            #pragma unroll
            for (int i = 0; i < 4; ++i) pa[i] = sP[(r0 + i) * 64 + k];
            #pragma unroll
            for (int j = 0; j < 4; ++j) pb[j] = sP[k * 64 + c0 + j];
            #pragma unroll
            for (int i = 0; i < 4; ++i)
                #pragma unroll
                for (int j = 0; j < 4; ++j) a[i][j] += pa[i] * pb[j];
        }
        #pragma unroll
        for (int i = 0; i < 4; ++i)
            #pragma unroll
            for (int j = 0; j < 4; ++j) sQ[(r0 + i) * 64 + c0 + j] = a[i][j];
    }
    __syncthreads();

    // wm_hat = I - P/2 + 3/8 Q - 5/16 (Q@P);  E = wm_hat*rs - I
    const float rs = sRs;
    {
        float a[4][4] = {};  // Q@P block
        for (int k = 0; k < 64; ++k) {
            float pa[4], pb[4];
            #pragma unroll
            for (int i = 0; i < 4; ++i) pa[i] = sQ[(r0 + i) * 64 + k];
            #pragma unroll
            for (int j = 0; j < 4; ++j) pb[j] = sP[k * 64 + c0 + j];
            #pragma unroll
            for (int i = 0; i < 4; ++i)
                #pragma unroll
                for (int j = 0; j < 4; ++j) a[i][j] += pa[i] * pb[j];
        }
        #pragma unroll
        for (int i = 0; i < 4; ++i) {
            #pragma unroll
            for (int j = 0; j < 4; ++j) {
                int idx = (r0 + i) * 64 + (c0 + j);
                float dlt = (r0 + i == c0 + j) ? 1.0f : 0.0f;
                float wmh = dlt - 0.5f * sP[idx] + 0.375f * sQ[idx] - 0.3125f * a[i][j];
                g_E[idx] = __float2bfloat16(wmh * rs - dlt);
            }
        }
    }
}

// ---------------------------------------------------------------------------
// Kernel 4: whiten  out = xc + E @ xc  (fp32 identity path + bf16 correction)
// ---------------------------------------------------------------------------
__global__ __launch_bounds__(256) void whiten_kernel(const float* __restrict__ X,
                                                     float* __restrict__ Y) {
    __shared__ float          tf[NC * FPITCH];   // fp32 centered tile
    __shared__ __nv_bfloat16  tb[NC * BPITCH];   // bf16 centered tile
    __shared__ __nv_bfloat16  sE[NC * BPITCH];   // E = wm - I
    __shared__ float          smean[NC];

    const int t = threadIdx.x, b = blockIdx.x;
    const int warp = t >> 5;

    if (t < NC) smean[t] = g_mean[t];
    for (int i = t; i < 4096; i += 256)
        sE[(i >> 6) * BPITCH + (i & 63)] = g_E[i];
    __syncthreads();

    const int row = t >> 2;
    const int c4  = (t & 3) * 4;
    const float mu = smean[row];

    for (int it = 0; it < 8; ++it) {
        const int T  = b + it * WBLK;
        const int n  = T / 49;
        const int s0 = (T % 49) * KT;
        const float4* src = (const float4*)(X + (size_t)n * NC * SS + (size_t)row * SS + s0);
        #pragma unroll
        for (int j = 0; j < 4; ++j) {
            float4 v = src[c4 + j];
            v.x -= mu; v.y -= mu; v.z -= mu; v.w -= mu;
            *(float4*)&tf[row * FPITCH + (c4 + j) * 4] = v;
            __nv_bfloat162* dst = (__nv_bfloat162*)&tb[row * BPITCH + (c4 + j) * 4];
            dst[0] = __floats2bfloat162_rn(v.x, v.y);
            dst[1] = __floats2bfloat162_rn(v.z, v.w);
        }
        __syncthreads();

        #pragma unroll
        for (int ot = 0; ot < 2; ++ot) {
            const int Tid = warp * 2 + ot;
            const int r0 = (Tid >> 2) * 16;   // output channel block
            const int q0 = (Tid & 3) * 16;    // s block
            wmma::fragment<wmma::accumulator, 16, 16, 16, float> acc;
            // accumulator initialized with fp32 xc -> identity path at full precision
            wmma::load_matrix_sync(acc, &tf[r0 * FPITCH + q0], FPITCH, wmma::mem_row_major);
            #pragma unroll
            for (int k = 0; k < 4; ++k) {
                wmma::fragment<wmma::matrix_a, 16, 16, 16, __nv_bfloat16, wmma::row_major> fa;
                wmma::fragment<wmma::matrix_b, 16, 16, 16, __nv_bfloat16, wmma::row_major> fb;
                wmma::load_matrix_sync(fa, &sE[r0 * BPITCH + k * 16], BPITCH);
                wmma::load_matrix_sync(fb, &tb[(k * 16) * BPITCH + q0], BPITCH);
                wmma::mma_sync(acc, fa, fb, acc);
            }
            wmma::store_matrix_sync(
                Y + (size_t)n * NC * SS + (size_t)r0 * SS + s0 + q0,
                acc, SS, wmma::mem_row_major);
        }
        __syncthreads();
    }
}

// ---------------------------------------------------------------------------
extern "C" void kernel_launch(void* const* d_in, const int* in_sizes, int n_in,
                              void* d_out, int out_size) {
    (void)in_sizes; (void)n_in; (void)out_size;
    const float* X = (const float*)d_in[0];
    float* Y = (float*)d_out;

    gram_kernel<<<GBLK, 256>>>(X);
    reduce_kernel<<<17, 256>>>();
    stats_kernel<<<1, 256>>>();
    whiten_kernel<<<WBLK, 256>>>(X, Y);
}

// round 4
// speedup vs baseline: 1.1039x; 1.1039x over previous
#include <cuda_runtime.h>
#include <cuda_bf16.h>
#include <mma.h>

using namespace nvcuda;

// Problem constants
#define NC     64          // channels
#define SS     3136        // 56*56
#define NIMG   128
#define MTOT   (NIMG*SS)   // 401408
#define KT     64          // s-tile width
#define TILES  (NIMG*49)   // 6272 tiles of 64 columns
#define GBLK   448         // gram grid (6272/448 = 14 tiles/block, exact)
#define WBLK   784         // whiten grid (6272/784 = 8 tiles/block, exact)
#define BPITCH 72          // bf16 smem pitch (mult of 8 elems = 16B)
#define FPITCH 68          // fp32 smem pitch (mult of 4 elems = 16B)
#define EPSF   1e-3f

// Scratch (static device globals: allocation-free)
__device__ float          g_partials[GBLK][4160]; // 4096 gram + 64 channel sums
__device__ float          g_G[4160];
__device__ float          g_mean[NC];
__device__ __nv_bfloat16  g_E[NC*NC];             // wm - I, row-major [c_out][c_in]

// ---------------------------------------------------------------------------
// Kernel 1: partial Gram G_b = sum over block's columns of x x^T, + channel sums
// Strip-mined warps (16x32 per warp) + software prefetch of next tile.
// ---------------------------------------------------------------------------
__global__ __launch_bounds__(256) void gram_kernel(const float* __restrict__ X) {
    __shared__ __nv_bfloat16 tb[NC * BPITCH];
    __shared__ float ssum[NC];

    const int t = threadIdx.x, b = blockIdx.x;
    const int warp = t >> 5;
    const int row = t >> 2;          // channel row 0..63 (fixed per thread)
    const int c4  = (t & 3) * 4;     // first float4 index (4 consecutive f4/thread)

    const int r0 = (warp >> 1) * 16;     // output row block (strip)
    const int q0 = (warp & 1) * 32;      // output col base (two 16-wide blocks)

    wmma::fragment<wmma::accumulator, 16, 16, 16, float> acc[2];
    wmma::fill_fragment(acc[0], 0.0f);
    wmma::fill_fragment(acc[1], 0.0f);

    float lsum = 0.0f;

    // prefetch tile 0
    float4 cur[4];
    {
        const int T  = b;
        const int n  = T / 49;
        const int s0 = (T % 49) * KT;
        const float4* src = (const float4*)(X + (size_t)n * NC * SS + (size_t)row * SS + s0);
        #pragma unroll
        for (int j = 0; j < 4; ++j) cur[j] = src[c4 + j];
    }

    for (int it = 0; it < 14; ++it) {
        // convert current tile to bf16 smem + accumulate channel sum
        #pragma unroll
        for (int j = 0; j < 4; ++j) {
            float4 v = cur[j];
            lsum += v.x + v.y + v.z + v.w;
            __nv_bfloat162* dst = (__nv_bfloat162*)&tb[row * BPITCH + (c4 + j) * 4];
            dst[0] = __floats2bfloat162_rn(v.x, v.y);
            dst[1] = __floats2bfloat162_rn(v.z, v.w);
        }
        __syncthreads();

        // prefetch next tile (overlaps with MMA below)
        if (it < 13) {
            const int T  = b + (it + 1) * GBLK;
            const int n  = T / 49;
            const int s0 = (T % 49) * KT;
            const float4* src = (const float4*)(X + (size_t)n * NC * SS + (size_t)row * SS + s0);
            #pragma unroll
            for (int j = 0; j < 4; ++j) cur[j] = src[c4 + j];
        }

        #pragma unroll
        for (int k = 0; k < 4; ++k) {
            wmma::fragment<wmma::matrix_a, 16, 16, 16, __nv_bfloat16, wmma::row_major> fa;
            wmma::fragment<wmma::matrix_b, 16, 16, 16, __nv_bfloat16, wmma::col_major> fb0, fb1;
            wmma::load_matrix_sync(fa, &tb[r0 * BPITCH + k * 16], BPITCH);
            wmma::load_matrix_sync(fb0, &tb[q0 * BPITCH + k * 16], BPITCH);
            wmma::load_matrix_sync(fb1, &tb[(q0 + 16) * BPITCH + k * 16], BPITCH);
            wmma::mma_sync(acc[0], fa, fb0, acc[0]);
            wmma::mma_sync(acc[1], fa, fb1, acc[1]);
        }
        __syncthreads();
    }

    // channel-sum reduce: 4 consecutive lanes share a row
    lsum += __shfl_down_sync(0xffffffffu, lsum, 2);
    lsum += __shfl_down_sync(0xffffffffu, lsum, 1);
    if ((t & 3) == 0) ssum[row] = lsum;
    __syncthreads();

    wmma::store_matrix_sync(&g_partials[b][r0 * 64 + q0],      acc[0], 64, wmma::mem_row_major);
    wmma::store_matrix_sync(&g_partials[b][r0 * 64 + q0 + 16], acc[1], 64, wmma::mem_row_major);
    if (t < NC) g_partials[b][4096 + t] = ssum[t];
}

// ---------------------------------------------------------------------------
// Kernel 2: reduce 448 partials -> g_G
// ---------------------------------------------------------------------------
__global__ __launch_bounds__(256) void reduce_kernel() {
    const int i = blockIdx.x * blockDim.x + threadIdx.x;
    if (i < 4160) {
        float s = 0.0f;
        #pragma unroll 4
        for (int b = 0; b < GBLK; ++b) s += g_partials[b][i];
        g_G[i] = s;
    }
}

// ---------------------------------------------------------------------------
// Kernel 3: single-block stats: sigma -> Taylor inverse-sqrt -> E = wm - I (bf16)
// ---------------------------------------------------------------------------
__global__ __launch_bounds__(256) void stats_kernel() {
    __shared__ float sP[4096];   // P = sigma/mu - I
    __shared__ float sQ[4096];   // Q = P*P
    __shared__ float smean[NC];
    __shared__ float sMu, sRs;

    const int t = threadIdx.x;
    const float invm = 1.0f / (float)MTOT;

    if (t < NC) {
        float mn = g_G[4096 + t] * invm;
        smean[t] = mn;
        g_mean[t] = mn;
    }
    __syncthreads();

    // sigma into sP
    for (int i = t; i < 4096; i += 256) {
        int r = i >> 6, c = i & 63;
        sP[i] = g_G[i] * invm - smean[r] * smean[c] + ((r == c) ? EPSF : 0.0f);
    }
    __syncthreads();

    if (t == 0) {
        float tr = 0.0f;
        for (int i = 0; i < NC; ++i) tr += sP[i * 65];
        float mu = tr / (float)NC;
        sMu = mu;
        float rs = rsqrtf(mu);
        rs = rs * (1.5f - 0.5f * mu * rs * rs);  // Newton refine
        sRs = rs;
    }
    __syncthreads();

    const float invmu = 1.0f / sMu;
    for (int i = t; i < 4096; i += 256) {
        int r = i >> 6, c = i & 63;
        sP[i] = sP[i] * invmu - ((r == c) ? 1.0f : 0.0f);
    }
    __syncthreads();

    // Q = P @ P : each thread owns a 4x4 output block (broadcast-friendly reads)
    const int r0 = (t >> 4) * 4;
    const int c0 = (t & 15) * 4;
    {
        float a[4][4] = {};
        for (int k = 0; k < 64; ++k) {
            float pa[4], pb[4];
            #pragma unroll
            for (int i = 0; i < 4; ++i) pa[i] = sP[(r0 + i) * 64 + k];
            #pragma unroll
            for (int j = 0; j < 4; ++j) pb[j] = sP[k * 64 + c0 + j];
            #pragma unroll
            for (int i = 0; i < 4; ++i)
                #pragma unroll
                for (int j = 0; j < 4; ++j) a[i][j] += pa[i] * pb[j];
        }
        #pragma unroll
        for (int i = 0; i < 4; ++i)
            #pragma unroll
            for (int j = 0; j < 4; ++j) sQ[(r0 + i) * 64 + c0 + j] = a[i][j];
    }
    __syncthreads();

    // wm_hat = I - P/2 + 3/8 Q - 5/16 (Q@P);  E = wm_hat*rs - I
    const float rs = sRs;
    {
        float a[4][4] = {};  // Q@P block
        for (int k = 0; k < 64; ++k) {
            float pa[4], pb[4];
            #pragma unroll
            for (int i = 0; i < 4; ++i) pa[i] = sQ[(r0 + i) * 64 + k];
            #pragma unroll
            for (int j = 0; j < 4; ++j) pb[j] = sP[k * 64 + c0 + j];
            #pragma unroll
            for (int i = 0; i < 4; ++i)
                #pragma unroll
                for (int j = 0; j < 4; ++j) a[i][j] += pa[i] * pb[j];
        }
        #pragma unroll
        for (int i = 0; i < 4; ++i) {
            #pragma unroll
            for (int j = 0; j < 4; ++j) {
                int idx = (r0 + i) * 64 + (c0 + j);
                float dlt = (r0 + i == c0 + j) ? 1.0f : 0.0f;
                float wmh = dlt - 0.5f * sP[idx] + 0.375f * sQ[idx] - 0.3125f * a[i][j];
                g_E[idx] = __float2bfloat16(wmh * rs - dlt);
            }
        }
    }
}

// ---------------------------------------------------------------------------
// Kernel 4: whiten  out = xc + E @ xc
// fp32 identity path carried in REGISTERS; bf16 tensor-core correction goes
// through a smem round-trip; fully coalesced float4 stores. Strip-mined warps
// + software prefetch of the next tile.
// ---------------------------------------------------------------------------
__global__ __launch_bounds__(256) void whiten_kernel(const float* __restrict__ X,
                                                     float* __restrict__ Y) {
    __shared__ __nv_bfloat16  tb[NC * BPITCH];    // bf16 centered tile
    __shared__ __nv_bfloat16  sE[NC * BPITCH];    // E = wm - I
    __shared__ float          corr[NC * FPITCH];  // fp32 correction tile
    __shared__ float          smean[NC];

    const int t = threadIdx.x, b = blockIdx.x;
    const int warp = t >> 5;

    if (t < NC) smean[t] = g_mean[t];
    for (int i = t; i < 4096; i += 256)
        sE[(i >> 6) * BPITCH + (i & 63)] = g_E[i];
    __syncthreads();

    const int row = t >> 2;
    const int c4  = (t & 3) * 4;
    const float mu = smean[row];

    const int r0 = (warp >> 1) * 16;   // output channel strip
    const int q0 = (warp & 1) * 32;    // s base (two 16-wide blocks)

    // prefetch tile 0
    float4 cur[4];
    {
        const int T  = b;
        const int n  = T / 49;
        const int s0 = (T % 49) * KT;
        const float4* src = (const float4*)(X + (size_t)n * NC * SS + (size_t)row * SS + s0);
        #pragma unroll
        for (int j = 0; j < 4; ++j) cur[j] = src[c4 + j];
    }

    for (int it = 0; it < 8; ++it) {
        const int T  = b + it * WBLK;
        const int n  = T / 49;
        const int s0 = (T % 49) * KT;

        // center in registers (keep xc!) and write bf16 tile
        #pragma unroll
        for (int j = 0; j < 4; ++j) {
            cur[j].x -= mu; cur[j].y -= mu; cur[j].z -= mu; cur[j].w -= mu;
            __nv_bfloat162* dst = (__nv_bfloat162*)&tb[row * BPITCH + (c4 + j) * 4];
            dst[0] = __floats2bfloat162_rn(cur[j].x, cur[j].y);
            dst[1] = __floats2bfloat162_rn(cur[j].z, cur[j].w);
        }
        __syncthreads();

        // prefetch next tile (overlaps with MMA)
        float4 nxt[4];
        if (it < 7) {
            const int Tn  = b + (it + 1) * WBLK;
            const int nn  = Tn / 49;
            const int sn  = (Tn % 49) * KT;
            const float4* src = (const float4*)(X + (size_t)nn * NC * SS + (size_t)row * SS + sn);
            #pragma unroll
            for (int j = 0; j < 4; ++j) nxt[j] = src[c4 + j];
        }

        // correction = E @ xc  (zero-init accumulators)
        wmma::fragment<wmma::accumulator, 16, 16, 16, float> acc0, acc1;
        wmma::fill_fragment(acc0, 0.0f);
        wmma::fill_fragment(acc1, 0.0f);
        #pragma unroll
        for (int k = 0; k < 4; ++k) {
            wmma::fragment<wmma::matrix_a, 16, 16, 16, __nv_bfloat16, wmma::row_major> fa;
            wmma::fragment<wmma::matrix_b, 16, 16, 16, __nv_bfloat16, wmma::row_major> fb0, fb1;
            wmma::load_matrix_sync(fa,  &sE[r0 * BPITCH + k * 16], BPITCH);
            wmma::load_matrix_sync(fb0, &tb[(k * 16) * BPITCH + q0], BPITCH);
            wmma::load_matrix_sync(fb1, &tb[(k * 16) * BPITCH + q0 + 16], BPITCH);
            wmma::mma_sync(acc0, fa, fb0, acc0);
            wmma::mma_sync(acc1, fa, fb1, acc1);
        }
        wmma::store_matrix_sync(&corr[r0 * FPITCH + q0],      acc0, FPITCH, wmma::mem_row_major);
        wmma::store_matrix_sync(&corr[r0 * FPITCH + q0 + 16], acc1, FPITCH, wmma::mem_row_major);
        __syncthreads();

        // out = xc (regs, fp32) + correction (smem) — coalesced float4 stores
        float* Yrow = Y + (size_t)n * NC * SS + (size_t)row * SS + s0;
        #pragma unroll
        for (int j = 0; j < 4; ++j) {
            float4 c = *(const float4*)&corr[row * FPITCH + (c4 + j) * 4];
            c.x += cur[j].x; c.y += cur[j].y; c.z += cur[j].z; c.w += cur[j].w;
            *(float4*)&Yrow[(c4 + j) * 4] = c;
        }

        #pragma unroll
        for (int j = 0; j < 4; ++j) cur[j] = nxt[j];
        // NOTE: next iteration's tb writes precede its __syncthreads(), and our
        // corr reads above precede those writes in program order; the sync after
        // the tb writes orders everything. No extra barrier needed here.
    }
}

// ---------------------------------------------------------------------------
extern "C" void kernel_launch(void* const* d_in, const int* in_sizes, int n_in,
                              void* d_out, int out_size) {
    (void)in_sizes; (void)n_in; (void)out_size;
    const float* X = (const float*)d_in[0];
    float* Y = (float*)d_out;

    gram_kernel<<<GBLK, 256>>>(X);
    reduce_kernel<<<17, 256>>>();
    stats_kernel<<<1, 256>>>();
    whiten_kernel<<<WBLK, 256>>>(X, Y);
}